// round 5
// baseline (speedup 1.0000x reference)
#include <cuda_runtime.h>
#include <cstdint>

#define N_NODES 100000
#define N_EDGES 1600000
#define IN_DIM 32
#define OUT_DIM 64
#define N_REL 8
#define K_DIM 256
#define K_TOT 288
#define N_GRP 36                  // 36 groups of 8 k-values (32 update + 4 x)
#define N_KSTEP 36
#define EPS 1e-10f

static constexpr int NROWTILES = N_NODES / 16;          // 6250 exact
#define TILE_FLOATS (N_GRP * 128)                        // 4608 floats per node-tile

// Scratch: fragment-native layout
//   g_A[ ((t*36 + grp)*16 + r)*8 + c ],  node = t*16+r
//   within a group, k-permutation: pos(2*i)=k(i), pos(2*i+1)=k(i+4), i=0..3
__device__ float g_A[(size_t)NROWTILES * TILE_FLOATS];   // 28.8M floats
__device__ float g_den[(size_t)N_NODES * N_REL];

__device__ __forceinline__ float to_tf32(float v) {
    uint32_t r;
    asm("cvt.rna.tf32.f32 %0, %1;" : "=r"(r) : "f"(v));
    return __uint_as_float(r);
}

// ---------------------------------------------------------------------------
// Kernel 1: pack x into groups 32..35 of g_A (permuted)
// ---------------------------------------------------------------------------
__global__ void xcopy_kernel(const float* __restrict__ x) {
    const int idx = blockIdx.x * blockDim.x + threadIdx.x;
    if (idx >= N_NODES * 4) return;
    const int node = idx >> 2;
    const int q    = idx & 3;
    const float4* xr = reinterpret_cast<const float4*>(x + (size_t)node * IN_DIM);
    const float4 u = xr[2 * q];       // k = q*8 + 0..3
    const float4 v = xr[2 * q + 1];   // k = q*8 + 4..7
    const int t = node >> 4, r = node & 15;
    float4* dst = reinterpret_cast<float4*>(
        g_A + ((size_t)t * N_GRP + 32 + q) * 128 + r * 8);
    dst[0] = make_float4(u.x, v.x, u.y, v.y);
    dst[1] = make_float4(u.z, v.z, u.w, v.w);
}

// ---------------------------------------------------------------------------
// Kernel 2: edge scatter into permuted layout (same atomic traffic as before)
// ---------------------------------------------------------------------------
__global__ void scatter_kernel(const int* __restrict__ edge_list,
                               const float* __restrict__ edge_weight,
                               const float* __restrict__ x) {
    const int e = blockIdx.x * blockDim.x + threadIdx.x;
    if (e >= N_EDGES) return;
    const int src = edge_list[3 * e + 0];
    const int dst = edge_list[3 * e + 1];
    const int rel = edge_list[3 * e + 2];
    const float w = edge_weight[e];

    const float4* xr = reinterpret_cast<const float4*>(x + (size_t)src * IN_DIM);
    float4 xv[8];
#pragma unroll
    for (int i = 0; i < 8; i++) xv[i] = xr[i];

    const int t = dst >> 4, r = dst & 15;
    float* tb = g_A + ((size_t)t * N_GRP + rel * 4) * 128 + r * 8;

#pragma unroll
    for (int q = 0; q < 4; q++) {
        const float4 u = xv[2 * q], v = xv[2 * q + 1];
        asm volatile(
            "red.global.add.v4.f32 [%0], {%1, %2, %3, %4};"
            :: "l"(tb + q * 128),
               "f"(u.x * w), "f"(v.x * w), "f"(u.y * w), "f"(v.y * w)
            : "memory");
        asm volatile(
            "red.global.add.v4.f32 [%0], {%1, %2, %3, %4};"
            :: "l"(tb + q * 128 + 4),
               "f"(u.z * w), "f"(v.z * w), "f"(u.w * w), "f"(v.w * w)
            : "memory");
    }
    atomicAdd(g_den + (size_t)dst * N_REL + rel, w);
}

// ---------------------------------------------------------------------------
// Kernel 3: warp-autonomous tf32 MMA GEMM over fragment-native g_A.
// ---------------------------------------------------------------------------
#define BF_FLOAT2 (N_KSTEP * 8 * 32)
#define BF_BYTES  (BF_FLOAT2 * 8)               // 73728
#define SMEM_TOTAL (BF_BYTES + OUT_DIM * 4)

__device__ __forceinline__ void mma_tf32(float c[4], uint32_t a0, uint32_t a1,
                                         uint32_t a2, uint32_t a3,
                                         uint32_t b0, uint32_t b1) {
    asm volatile(
        "mma.sync.aligned.m16n8k8.row.col.f32.tf32.tf32.f32 "
        "{%0,%1,%2,%3}, {%4,%5,%6,%7}, {%8,%9}, {%0,%1,%2,%3};"
        : "+f"(c[0]), "+f"(c[1]), "+f"(c[2]), "+f"(c[3])
        : "r"(a0), "r"(a1), "r"(a2), "r"(a3), "r"(b0), "r"(b1));
}

__global__ __launch_bounds__(512, 1)
void gemm_mma_kernel(const float* __restrict__ Wl,
                     const float* __restrict__ bl,
                     const float* __restrict__ Ws,
                     const float* __restrict__ bs,
                     float* __restrict__ out) {
    extern __shared__ char smem[];
    float2* sBf   = reinterpret_cast<float2*>(smem);
    float*  sBias = reinterpret_cast<float*>(smem + BF_BYTES);

    const int tid  = threadIdx.x;
    const int wid  = tid >> 5;
    const int lane = tid & 31;
    const int g    = lane >> 2;
    const int tig  = lane & 3;

    // ---- stage B fragments once: sBf[(s*8+j)*32 + lane] = (W[k0][n], W[k1][n]) ----
    for (int idx = tid; idx < BF_FLOAT2; idx += 512) {
        const int l  = idx & 31;
        const int j  = (idx >> 5) & 7;
        const int s  = idx >> 8;
        const int gg = l >> 2, tt = l & 3;
        const int n  = j * 8 + gg;
        const int k0 = s * 8 + tt;
        const int k1 = k0 + 4;
        const float v0 = (k0 < K_DIM) ? Wl[(size_t)k0 * OUT_DIM + n]
                                      : Ws[(size_t)(k0 - K_DIM) * OUT_DIM + n];
        const float v1 = (k1 < K_DIM) ? Wl[(size_t)k1 * OUT_DIM + n]
                                      : Ws[(size_t)(k1 - K_DIM) * OUT_DIM + n];
        sBf[idx] = make_float2(to_tf32(v0), to_tf32(v1));
    }
    if (tid < OUT_DIM) sBias[tid] = bl[tid] + bs[tid];
    __syncthreads();

    const int nwarps = gridDim.x * 16;

    for (int t = blockIdx.x * 16 + wid; t < NROWTILES; t += nwarps) {
        const int row0 = t * 16 + g;
        const int row1 = row0 + 8;

        // ---- 1/den for both rows ----
        float dinv0[8], dinv1[8];
        {
            const float4* d0 = reinterpret_cast<const float4*>(g_den + (size_t)row0 * N_REL);
            const float4* d1 = reinterpret_cast<const float4*>(g_den + (size_t)row1 * N_REL);
            float4 a = d0[0], b = d0[1], c = d1[0], d = d1[1];
            dinv0[0] = __fdividef(1.f, a.x + EPS); dinv0[1] = __fdividef(1.f, a.y + EPS);
            dinv0[2] = __fdividef(1.f, a.z + EPS); dinv0[3] = __fdividef(1.f, a.w + EPS);
            dinv0[4] = __fdividef(1.f, b.x + EPS); dinv0[5] = __fdividef(1.f, b.y + EPS);
            dinv0[6] = __fdividef(1.f, b.z + EPS); dinv0[7] = __fdividef(1.f, b.w + EPS);
            dinv1[0] = __fdividef(1.f, c.x + EPS); dinv1[1] = __fdividef(1.f, c.y + EPS);
            dinv1[2] = __fdividef(1.f, c.z + EPS); dinv1[3] = __fdividef(1.f, c.w + EPS);
            dinv1[4] = __fdividef(1.f, d.x + EPS); dinv1[5] = __fdividef(1.f, d.y + EPS);
            dinv1[6] = __fdividef(1.f, d.z + EPS); dinv1[7] = __fdividef(1.f, d.w + EPS);
        }

        float acc[8][4];
#pragma unroll
        for (int j = 0; j < 8; j++)
#pragma unroll
            for (int c = 0; c < 4; c++) acc[j][c] = 0.f;

        const float* At = g_A + (size_t)t * TILE_FLOATS;
        const int off0 = g * 8 + tig * 2;          // row0 pair offset in group
        const int off1 = (g + 8) * 8 + tig * 2;    // row1

        // ---- update part: groups 0..31 (with 1/den) ----
#pragma unroll 4
        for (int s = 0; s < 32; s++) {
            const float2 p0 = *reinterpret_cast<const float2*>(At + s * 128 + off0);
            const float2 p1 = *reinterpret_cast<const float2*>(At + s * 128 + off1);
            const float d0 = dinv0[s >> 2], d1 = dinv1[s >> 2];
            const uint32_t a0 = __float_as_uint(to_tf32(p0.x * d0));
            const uint32_t a2 = __float_as_uint(to_tf32(p0.y * d0));
            const uint32_t a1 = __float_as_uint(to_tf32(p1.x * d1));
            const uint32_t a3 = __float_as_uint(to_tf32(p1.y * d1));
            const float2* bf = sBf + s * 256 + lane;
#pragma unroll
            for (int j = 0; j < 8; j++) {
                const float2 bb = bf[j * 32];
                mma_tf32(acc[j], a0, a1, a2, a3,
                         __float_as_uint(bb.x), __float_as_uint(bb.y));
            }
        }
        // ---- x part: groups 32..35 (no normalization) ----
#pragma unroll
        for (int s = 32; s < 36; s++) {
            const float2 p0 = *reinterpret_cast<const float2*>(At + s * 128 + off0);
            const float2 p1 = *reinterpret_cast<const float2*>(At + s * 128 + off1);
            const uint32_t a0 = __float_as_uint(to_tf32(p0.x));
            const uint32_t a2 = __float_as_uint(to_tf32(p0.y));
            const uint32_t a1 = __float_as_uint(to_tf32(p1.x));
            const uint32_t a3 = __float_as_uint(to_tf32(p1.y));
            const float2* bf = sBf + s * 256 + lane;
#pragma unroll
            for (int j = 0; j < 8; j++) {
                const float2 bb = bf[j * 32];
                mma_tf32(acc[j], a0, a1, a2, a3,
                         __float_as_uint(bb.x), __float_as_uint(bb.y));
            }
        }

        // ---- epilogue: bias + relu + float2 stores ----
#pragma unroll
        for (int j = 0; j < 8; j++) {
            const int col = j * 8 + tig * 2;
            const float b0 = sBias[col], b1 = sBias[col + 1];
            float2 v0 = make_float2(fmaxf(acc[j][0] + b0, 0.f),
                                    fmaxf(acc[j][1] + b1, 0.f));
            float2 v1 = make_float2(fmaxf(acc[j][2] + b0, 0.f),
                                    fmaxf(acc[j][3] + b1, 0.f));
            *reinterpret_cast<float2*>(out + (size_t)row0 * OUT_DIM + col) = v0;
            *reinterpret_cast<float2*>(out + (size_t)row1 * OUT_DIM + col) = v1;
        }
    }
}

// ---------------------------------------------------------------------------
// Launch
// ---------------------------------------------------------------------------
extern "C" void kernel_launch(void* const* d_in, const int* in_sizes, int n_in,
                              void* d_out, int out_size) {
    const float* x     = (const float*)d_in[0];
    const int*   edges = (const int*)  d_in[1];
    const float* ew    = (const float*)d_in[2];
    const float* Wl    = (const float*)d_in[3];
    const float* bl    = (const float*)d_in[4];
    const float* Ws    = (const float*)d_in[5];
    const float* bs    = (const float*)d_in[6];
    float*       out   = (float*)d_out;

    void* pA = nullptr; void* pden = nullptr;
    cudaGetSymbolAddress(&pA, g_A);
    cudaGetSymbolAddress(&pden, g_den);
    // zero only the update groups (0..31); groups 32..35 are overwritten by xcopy.
    // simplest: zero everything (115 MB ≈ +1.6us vs 102 MB)
    cudaMemsetAsync(pA, 0, (size_t)NROWTILES * TILE_FLOATS * sizeof(float), 0);
    cudaMemsetAsync(pden, 0, (size_t)N_NODES * N_REL * sizeof(float), 0);

    xcopy_kernel<<<(N_NODES * 4 + 255) / 256, 256>>>(x);
    scatter_kernel<<<(N_EDGES + 255) / 256, 256>>>(edges, ew, x);

    cudaFuncSetAttribute(gemm_mma_kernel,
                         cudaFuncAttributeMaxDynamicSharedMemorySize,
                         SMEM_TOTAL);
    gemm_mma_kernel<<<148, 512, SMEM_TOTAL>>>(Wl, bl, Ws, bs, out);
}

// round 6
// speedup vs baseline: 1.4212x; 1.4212x over previous
#include <cuda_runtime.h>
#include <cstdint>

#define N_NODES 100000
#define N_EDGES 1600000
#define IN_DIM 32
#define OUT_DIM 64
#define N_REL 8
#define K_DIM 256
#define K_TOT 288
#define N_KSTEP 36
#define EPS 1e-10f

static constexpr int NROWTILES = N_NODES / 16;   // 6250 exact

// Scratch (alloc-free rule): ORIGINAL row-major layout — edge writes contiguous.
__device__ float g_num[(size_t)N_NODES * K_DIM];
__device__ float g_den[(size_t)N_NODES * N_REL];

__device__ __forceinline__ float to_tf32(float v) {
    uint32_t r;
    asm("cvt.rna.tf32.f32 %0, %1;" : "=r"(r) : "f"(v));
    return __uint_as_float(r);
}

// ---------------------------------------------------------------------------
// Kernel 1: edge scatter, 8 lanes per edge.
//   Per warp: 4 edges. Lanes 0-11 load edge_list, 12-15 load weights,
//   broadcast via shfl. Each edge's 8 lanes do one red.v4 each into a
//   single 128B-contiguous destination line; x gather is also one line.
// ---------------------------------------------------------------------------
__global__ void scatter_kernel(const int* __restrict__ edge_list,
                               const float* __restrict__ edge_weight,
                               const float* __restrict__ x) {
    const int tid   = threadIdx.x;
    const int gwarp = (blockIdx.x * blockDim.x + tid) >> 5;
    const int lane  = tid & 31;
    const int sub   = lane >> 3;      // edge slot within warp (0..3)
    const int i8    = lane & 7;       // float4 index within 32-float row

    const int e0 = gwarp * 4;         // N_EDGES % 4 == 0, grid sized exactly

    int   ev = 0;
    float wv = 0.f;
    if (lane < 12)               ev = edge_list[(size_t)e0 * 3 + lane];
    else if (lane < 16)          wv = edge_weight[e0 + (lane - 12)];

    const int   src = __shfl_sync(0xffffffffu, ev, sub * 3 + 0);
    const int   dst = __shfl_sync(0xffffffffu, ev, sub * 3 + 1);
    const int   rel = __shfl_sync(0xffffffffu, ev, sub * 3 + 2);
    const float w   = __shfl_sync(0xffffffffu, wv, 12 + sub);

    const float4 v =
        reinterpret_cast<const float4*>(x + (size_t)src * IN_DIM)[i8];
    float* basep = g_num + (size_t)dst * K_DIM + rel * IN_DIM + i8 * 4;

    asm volatile(
        "red.global.add.v4.f32 [%0], {%1, %2, %3, %4};"
        :: "l"(basep),
           "f"(v.x * w), "f"(v.y * w), "f"(v.z * w), "f"(v.w * w)
        : "memory");

    if (i8 == 0)
        atomicAdd(g_den + (size_t)dst * N_REL + rel, w);
}

// ---------------------------------------------------------------------------
// Kernel 2: warp-autonomous tf32 MMA GEMM (identical to R4 best).
// ---------------------------------------------------------------------------
#define BF_FLOAT2 (N_KSTEP * 8 * 32)
#define BF_BYTES  (BF_FLOAT2 * 8)               // 73728
#define SMEM_TOTAL (BF_BYTES + OUT_DIM * 4)

__device__ __forceinline__ void mma_tf32(float c[4], uint32_t a0, uint32_t a1,
                                         uint32_t a2, uint32_t a3,
                                         uint32_t b0, uint32_t b1) {
    asm volatile(
        "mma.sync.aligned.m16n8k8.row.col.f32.tf32.tf32.f32 "
        "{%0,%1,%2,%3}, {%4,%5,%6,%7}, {%8,%9}, {%0,%1,%2,%3};"
        : "+f"(c[0]), "+f"(c[1]), "+f"(c[2]), "+f"(c[3])
        : "r"(a0), "r"(a1), "r"(a2), "r"(a3), "r"(b0), "r"(b1));
}

__global__ __launch_bounds__(512, 1)
void gemm_mma_kernel(const float* __restrict__ x,
                     const float* __restrict__ Wl,
                     const float* __restrict__ bl,
                     const float* __restrict__ Ws,
                     const float* __restrict__ bs,
                     float* __restrict__ out) {
    extern __shared__ char smem[];
    float2* sBf   = reinterpret_cast<float2*>(smem);
    float*  sBias = reinterpret_cast<float*>(smem + BF_BYTES);

    const int tid  = threadIdx.x;
    const int wid  = tid >> 5;
    const int lane = tid & 31;
    const int g    = lane >> 2;
    const int tig  = lane & 3;

    for (int idx = tid; idx < BF_FLOAT2; idx += 512) {
        const int l  = idx & 31;
        const int j  = (idx >> 5) & 7;
        const int s  = idx >> 8;
        const int gg = l >> 2, tt = l & 3;
        const int n  = j * 8 + gg;
        const int k0 = s * 8 + tt;
        const int k1 = k0 + 4;
        const float v0 = (k0 < K_DIM) ? Wl[(size_t)k0 * OUT_DIM + n]
                                      : Ws[(size_t)(k0 - K_DIM) * OUT_DIM + n];
        const float v1 = (k1 < K_DIM) ? Wl[(size_t)k1 * OUT_DIM + n]
                                      : Ws[(size_t)(k1 - K_DIM) * OUT_DIM + n];
        sBf[idx] = make_float2(to_tf32(v0), to_tf32(v1));
    }
    if (tid < OUT_DIM) sBias[tid] = bl[tid] + bs[tid];
    __syncthreads();

    const int nwarps = gridDim.x * 16;

    for (int t = blockIdx.x * 16 + wid; t < NROWTILES; t += nwarps) {
        const int row0 = t * 16 + g;
        const int row1 = row0 + 8;

        float dinv0[8], dinv1[8];
        {
            const float4* d0 = reinterpret_cast<const float4*>(g_den + (size_t)row0 * N_REL);
            const float4* d1 = reinterpret_cast<const float4*>(g_den + (size_t)row1 * N_REL);
            float4 a = d0[0], b = d0[1], c = d1[0], d = d1[1];
            dinv0[0] = __fdividef(1.f, a.x + EPS); dinv0[1] = __fdividef(1.f, a.y + EPS);
            dinv0[2] = __fdividef(1.f, a.z + EPS); dinv0[3] = __fdividef(1.f, a.w + EPS);
            dinv0[4] = __fdividef(1.f, b.x + EPS); dinv0[5] = __fdividef(1.f, b.y + EPS);
            dinv0[6] = __fdividef(1.f, b.z + EPS); dinv0[7] = __fdividef(1.f, b.w + EPS);
            dinv1[0] = __fdividef(1.f, c.x + EPS); dinv1[1] = __fdividef(1.f, c.y + EPS);
            dinv1[2] = __fdividef(1.f, c.z + EPS); dinv1[3] = __fdividef(1.f, c.w + EPS);
            dinv1[4] = __fdividef(1.f, d.x + EPS); dinv1[5] = __fdividef(1.f, d.y + EPS);
            dinv1[6] = __fdividef(1.f, d.z + EPS); dinv1[7] = __fdividef(1.f, d.w + EPS);
        }

        float acc[8][4];
#pragma unroll
        for (int j = 0; j < 8; j++)
#pragma unroll
            for (int c = 0; c < 4; c++) acc[j][c] = 0.f;

        const float* A0 = g_num + (size_t)row0 * K_DIM;
        const float* A1 = g_num + (size_t)row1 * K_DIM;

#pragma unroll 8
        for (int s = 0; s < 32; s++) {
            const int k = s * 8 + tig;
            const int b = s >> 2;
            const uint32_t a0 = __float_as_uint(to_tf32(A0[k]     * dinv0[b]));
            const uint32_t a1 = __float_as_uint(to_tf32(A1[k]     * dinv1[b]));
            const uint32_t a2 = __float_as_uint(to_tf32(A0[k + 4] * dinv0[b]));
            const uint32_t a3 = __float_as_uint(to_tf32(A1[k + 4] * dinv1[b]));
            const float2* bf = sBf + s * 256 + lane;
#pragma unroll
            for (int j = 0; j < 8; j++) {
                const float2 bb = bf[j * 32];
                mma_tf32(acc[j], a0, a1, a2, a3,
                         __float_as_uint(bb.x), __float_as_uint(bb.y));
            }
        }

        const float* X0 = x + (size_t)row0 * IN_DIM;
        const float* X1 = x + (size_t)row1 * IN_DIM;
#pragma unroll
        for (int s = 32; s < 36; s++) {
            const int c = (s - 32) * 8 + tig;
            const uint32_t a0 = __float_as_uint(to_tf32(X0[c]));
            const uint32_t a1 = __float_as_uint(to_tf32(X1[c]));
            const uint32_t a2 = __float_as_uint(to_tf32(X0[c + 4]));
            const uint32_t a3 = __float_as_uint(to_tf32(X1[c + 4]));
            const float2* bf = sBf + s * 256 + lane;
#pragma unroll
            for (int j = 0; j < 8; j++) {
                const float2 bb = bf[j * 32];
                mma_tf32(acc[j], a0, a1, a2, a3,
                         __float_as_uint(bb.x), __float_as_uint(bb.y));
            }
        }

#pragma unroll
        for (int j = 0; j < 8; j++) {
            const int col = j * 8 + tig * 2;
            const float b0 = sBias[col], b1 = sBias[col + 1];
            float2 v0 = make_float2(fmaxf(acc[j][0] + b0, 0.f),
                                    fmaxf(acc[j][1] + b1, 0.f));
            float2 v1 = make_float2(fmaxf(acc[j][2] + b0, 0.f),
                                    fmaxf(acc[j][3] + b1, 0.f));
            *reinterpret_cast<float2*>(out + (size_t)row0 * OUT_DIM + col) = v0;
            *reinterpret_cast<float2*>(out + (size_t)row1 * OUT_DIM + col) = v1;
        }
    }
}

// ---------------------------------------------------------------------------
// Launch
// ---------------------------------------------------------------------------
extern "C" void kernel_launch(void* const* d_in, const int* in_sizes, int n_in,
                              void* d_out, int out_size) {
    const float* x     = (const float*)d_in[0];
    const int*   edges = (const int*)  d_in[1];
    const float* ew    = (const float*)d_in[2];
    const float* Wl    = (const float*)d_in[3];
    const float* bl    = (const float*)d_in[4];
    const float* Ws    = (const float*)d_in[5];
    const float* bs    = (const float*)d_in[6];
    float*       out   = (float*)d_out;

    void* pnum = nullptr; void* pden = nullptr;
    cudaGetSymbolAddress(&pnum, g_num);
    cudaGetSymbolAddress(&pden, g_den);
    cudaMemsetAsync(pnum, 0, (size_t)N_NODES * K_DIM * sizeof(float), 0);
    cudaMemsetAsync(pden, 0, (size_t)N_NODES * N_REL * sizeof(float), 0);

    // 8 lanes per edge: 1.6M * 8 = 12.8M threads = exactly 50000 blocks of 256
    scatter_kernel<<<(N_EDGES * 8) / 256, 256>>>(edges, ew, x);

    cudaFuncSetAttribute(gemm_mma_kernel,
                         cudaFuncAttributeMaxDynamicSharedMemorySize,
                         SMEM_TOTAL);
    gemm_mma_kernel<<<148, 512, SMEM_TOTAL>>>(x, Wl, bl, Ws, bs, out);
}

// round 7
// speedup vs baseline: 1.6181x; 1.1385x over previous
#include <cuda_runtime.h>
#include <cstdint>

#define N_NODES 100000
#define N_EDGES 1600000
#define IN_DIM 32
#define OUT_DIM 64
#define N_REL 8
#define K_DIM 256
#define K_TOT 288
#define N_KSTEP 36
#define EPS 1e-10f

static constexpr int NROWTILES = N_NODES / 16;   // 6250 exact

// Scratch (alloc-free rule): row-major layout — edge writes stay contiguous.
__device__ float g_num[(size_t)N_NODES * K_DIM];
__device__ float g_den[(size_t)N_NODES * N_REL];

__device__ __forceinline__ float to_tf32(float v) {
    uint32_t r;
    asm("cvt.rna.tf32.f32 %0, %1;" : "=r"(r) : "f"(v));
    return __uint_as_float(r);
}

// ---------------------------------------------------------------------------
// Kernel 1: edge scatter, 8 lanes per edge (unchanged from R6 best).
// ---------------------------------------------------------------------------
__global__ void scatter_kernel(const int* __restrict__ edge_list,
                               const float* __restrict__ edge_weight,
                               const float* __restrict__ x) {
    const int tid   = threadIdx.x;
    const int gwarp = (blockIdx.x * blockDim.x + tid) >> 5;
    const int lane  = tid & 31;
    const int sub   = lane >> 3;
    const int i8    = lane & 7;

    const int e0 = gwarp * 4;

    int   ev = 0;
    float wv = 0.f;
    if (lane < 12)      ev = edge_list[(size_t)e0 * 3 + lane];
    else if (lane < 16) wv = edge_weight[e0 + (lane - 12)];

    const int   src = __shfl_sync(0xffffffffu, ev, sub * 3 + 0);
    const int   dst = __shfl_sync(0xffffffffu, ev, sub * 3 + 1);
    const int   rel = __shfl_sync(0xffffffffu, ev, sub * 3 + 2);
    const float w   = __shfl_sync(0xffffffffu, wv, 12 + sub);

    const float4 v =
        reinterpret_cast<const float4*>(x + (size_t)src * IN_DIM)[i8];
    float* basep = g_num + (size_t)dst * K_DIM + rel * IN_DIM + i8 * 4;

    asm volatile(
        "red.global.add.v4.f32 [%0], {%1, %2, %3, %4};"
        :: "l"(basep),
           "f"(v.x * w), "f"(v.y * w), "f"(v.z * w), "f"(v.w * w)
        : "memory");

    if (i8 == 0)
        atomicAdd(g_den + (size_t)dst * N_REL + rel, w);
}

// ---------------------------------------------------------------------------
// Kernel 2: tf32 MMA GEMM with per-warp SMEM staging (coalesced A loads).
// ---------------------------------------------------------------------------
#define BF_FLOAT2 (N_KSTEP * 8 * 32)
#define BF_BYTES  (BF_FLOAT2 * 8)               // 73728
#define WBUF_STRIDE 36                          // padded row stride (floats)
#define WBUF_FLOATS (16 * WBUF_STRIDE)          // 576 per warp
#define WBUF_OFF   (BF_BYTES + OUT_DIM * 4)     // after B frags + bias
#define SMEM_TOTAL (WBUF_OFF + 16 * WBUF_FLOATS * 4)   // 110848

__device__ __forceinline__ void mma_tf32(float c[4], uint32_t a0, uint32_t a1,
                                         uint32_t a2, uint32_t a3,
                                         uint32_t b0, uint32_t b1) {
    asm volatile(
        "mma.sync.aligned.m16n8k8.row.col.f32.tf32.tf32.f32 "
        "{%0,%1,%2,%3}, {%4,%5,%6,%7}, {%8,%9}, {%0,%1,%2,%3};"
        : "+f"(c[0]), "+f"(c[1]), "+f"(c[2]), "+f"(c[3])
        : "r"(a0), "r"(a1), "r"(a2), "r"(a3), "r"(b0), "r"(b1));
}

__global__ __launch_bounds__(512, 1)
void gemm_mma_kernel(const float* __restrict__ x,
                     const float* __restrict__ Wl,
                     const float* __restrict__ bl,
                     const float* __restrict__ Ws,
                     const float* __restrict__ bs,
                     float* __restrict__ out) {
    extern __shared__ char smem[];
    float2* sBf   = reinterpret_cast<float2*>(smem);
    float*  sBias = reinterpret_cast<float*>(smem + BF_BYTES);

    const int tid  = threadIdx.x;
    const int wid  = tid >> 5;
    const int lane = tid & 31;
    const int g    = lane >> 2;
    const int tig  = lane & 3;

    float* wbuf = reinterpret_cast<float*>(smem + WBUF_OFF) + wid * WBUF_FLOATS;
    const int ldrow = lane >> 3;          // 0..3: row subgroup for staging
    const int ldcol = (lane & 7) * 4;     // float offset within 32-float chunk

    // ---- stage B fragments once ----
    for (int idx = tid; idx < BF_FLOAT2; idx += 512) {
        const int l  = idx & 31;
        const int j  = (idx >> 5) & 7;
        const int s  = idx >> 8;
        const int gg = l >> 2, tt = l & 3;
        const int n  = j * 8 + gg;
        const int k0 = s * 8 + tt;
        const int k1 = k0 + 4;
        const float v0 = (k0 < K_DIM) ? Wl[(size_t)k0 * OUT_DIM + n]
                                      : Ws[(size_t)(k0 - K_DIM) * OUT_DIM + n];
        const float v1 = (k1 < K_DIM) ? Wl[(size_t)k1 * OUT_DIM + n]
                                      : Ws[(size_t)(k1 - K_DIM) * OUT_DIM + n];
        sBf[idx] = make_float2(to_tf32(v0), to_tf32(v1));
    }
    if (tid < OUT_DIM) sBias[tid] = bl[tid] + bs[tid];
    __syncthreads();

    const int nwarps = gridDim.x * 16;

    for (int t = blockIdx.x * 16 + wid; t < NROWTILES; t += nwarps) {
        const int row0 = t * 16 + g;
        const int row1 = row0 + 8;

        // ---- 1/den ----
        float dinv0[8], dinv1[8];
        {
            const float4* d0 = reinterpret_cast<const float4*>(g_den + (size_t)row0 * N_REL);
            const float4* d1 = reinterpret_cast<const float4*>(g_den + (size_t)row1 * N_REL);
            float4 a = d0[0], b = d0[1], c = d1[0], d = d1[1];
            dinv0[0] = __fdividef(1.f, a.x + EPS); dinv0[1] = __fdividef(1.f, a.y + EPS);
            dinv0[2] = __fdividef(1.f, a.z + EPS); dinv0[3] = __fdividef(1.f, a.w + EPS);
            dinv0[4] = __fdividef(1.f, b.x + EPS); dinv0[5] = __fdividef(1.f, b.y + EPS);
            dinv0[6] = __fdividef(1.f, b.z + EPS); dinv0[7] = __fdividef(1.f, b.w + EPS);
            dinv1[0] = __fdividef(1.f, c.x + EPS); dinv1[1] = __fdividef(1.f, c.y + EPS);
            dinv1[2] = __fdividef(1.f, c.z + EPS); dinv1[3] = __fdividef(1.f, c.w + EPS);
            dinv1[4] = __fdividef(1.f, d.x + EPS); dinv1[5] = __fdividef(1.f, d.y + EPS);
            dinv1[6] = __fdividef(1.f, d.z + EPS); dinv1[7] = __fdividef(1.f, d.w + EPS);
        }

        float acc[8][4];
#pragma unroll
        for (int j = 0; j < 8; j++)
#pragma unroll
            for (int c = 0; c < 4; c++) acc[j][c] = 0.f;

        const float* srcA = g_num + (size_t)t * 16 * K_DIM;   // row r at +r*256
        const float* srcX = x + (size_t)t * 16 * IN_DIM;      // row r at +r*32

        // prefetch kblock 0 (coalesced: 8 lanes cover one 128B row-line)
        float4 pf[4];
#pragma unroll
        for (int i = 0; i < 4; i++)
            pf[i] = *reinterpret_cast<const float4*>(
                srcA + (size_t)(i * 4 + ldrow) * K_DIM + ldcol);

#pragma unroll
        for (int kb = 0; kb < 9; kb++) {
            // stage current block
#pragma unroll
            for (int i = 0; i < 4; i++)
                *reinterpret_cast<float4*>(
                    wbuf + (i * 4 + ldrow) * WBUF_STRIDE + ldcol) = pf[i];
            __syncwarp();

            // prefetch next block (overlaps with MMA below)
            if (kb < 7) {
#pragma unroll
                for (int i = 0; i < 4; i++)
                    pf[i] = *reinterpret_cast<const float4*>(
                        srcA + (size_t)(i * 4 + ldrow) * K_DIM + (kb + 1) * 32 + ldcol);
            } else if (kb == 7) {
#pragma unroll
                for (int i = 0; i < 4; i++)
                    pf[i] = *reinterpret_cast<const float4*>(
                        srcX + (size_t)(i * 4 + ldrow) * IN_DIM + ldcol);
            }

            const float d0 = (kb < 8) ? dinv0[kb] : 1.f;
            const float d1 = (kb < 8) ? dinv1[kb] : 1.f;

#pragma unroll
            for (int ss = 0; ss < 4; ss++) {
                const int kl = ss * 8 + tig;
                const float f0 = wbuf[g * WBUF_STRIDE + kl];
                const float f2 = wbuf[g * WBUF_STRIDE + kl + 4];
                const float f1 = wbuf[(g + 8) * WBUF_STRIDE + kl];
                const float f3 = wbuf[(g + 8) * WBUF_STRIDE + kl + 4];
                const uint32_t a0 = __float_as_uint(to_tf32(f0 * d0));
                const uint32_t a2 = __float_as_uint(to_tf32(f2 * d0));
                const uint32_t a1 = __float_as_uint(to_tf32(f1 * d1));
                const uint32_t a3 = __float_as_uint(to_tf32(f3 * d1));
                const float2* bf = sBf + (kb * 4 + ss) * 256 + lane;
#pragma unroll
                for (int j = 0; j < 8; j++) {
                    const float2 bb = bf[j * 32];
                    mma_tf32(acc[j], a0, a1, a2, a3,
                             __float_as_uint(bb.x), __float_as_uint(bb.y));
                }
            }
            __syncwarp();   // LDS done before next iteration's STS
        }

        // ---- epilogue ----
#pragma unroll
        for (int j = 0; j < 8; j++) {
            const int col = j * 8 + tig * 2;
            const float b0 = sBias[col], b1 = sBias[col + 1];
            float2 v0 = make_float2(fmaxf(acc[j][0] + b0, 0.f),
                                    fmaxf(acc[j][1] + b1, 0.f));
            float2 v1 = make_float2(fmaxf(acc[j][2] + b0, 0.f),
                                    fmaxf(acc[j][3] + b1, 0.f));
            *reinterpret_cast<float2*>(out + (size_t)row0 * OUT_DIM + col) = v0;
            *reinterpret_cast<float2*>(out + (size_t)row1 * OUT_DIM + col) = v1;
        }
    }
}

// ---------------------------------------------------------------------------
// Launch
// ---------------------------------------------------------------------------
extern "C" void kernel_launch(void* const* d_in, const int* in_sizes, int n_in,
                              void* d_out, int out_size) {
    const float* x     = (const float*)d_in[0];
    const int*   edges = (const int*)  d_in[1];
    const float* ew    = (const float*)d_in[2];
    const float* Wl    = (const float*)d_in[3];
    const float* bl    = (const float*)d_in[4];
    const float* Ws    = (const float*)d_in[5];
    const float* bs    = (const float*)d_in[6];
    float*       out   = (float*)d_out;

    void* pnum = nullptr; void* pden = nullptr;
    cudaGetSymbolAddress(&pnum, g_num);
    cudaGetSymbolAddress(&pden, g_den);
    cudaMemsetAsync(pnum, 0, (size_t)N_NODES * K_DIM * sizeof(float), 0);
    cudaMemsetAsync(pden, 0, (size_t)N_NODES * N_REL * sizeof(float), 0);

    scatter_kernel<<<(N_EDGES * 8) / 256, 256>>>(edges, ew, x);

    cudaFuncSetAttribute(gemm_mma_kernel,
                         cudaFuncAttributeMaxDynamicSharedMemorySize,
                         SMEM_TOTAL);
    gemm_mma_kernel<<<148, 512, SMEM_TOTAL>>>(x, Wl, bl, Ws, bs, out);
}